// round 17
// baseline (speedup 1.0000x reference)
#include <cuda_runtime.h>
#include <cstdint>

#define IN_CH  128
#define K_HOPS 3
#define MAX_N  10240
#define MAX_E  330000

#define TN     80          // nodes per GEMM block -> 125 blocks (single wave)
#define GTHR   512         // GEMM threads/block -> 16 warps/SM

// Scratch (__device__ globals: allocation-guard-safe)
__device__ float  g_agg[(size_t)MAX_N * K_HOPS * IN_CH];   // [n][k][c] 15.7 MB
__device__ float4 g_packed[MAX_E];      // {x0,x1,x2, bits(dst)} sorted by src
__device__ int    g_rank[MAX_E];
__device__ int    g_cnt[MAX_N + 1];
__device__ int    g_off[MAX_N + 1];
__device__ int    g_is64;

// ---------------------------------------------------------------------------
// f32x2 packed helpers (PTX ISA 8.6, sm_100+) and cp.async helpers (Ampere+)
// ---------------------------------------------------------------------------
__device__ __forceinline__ void ffma2(uint64_t& c, uint64_t a, uint64_t b) {
    asm("fma.rn.f32x2 %0, %1, %2, %0;" : "+l"(c) : "l"(a), "l"(b));
}
__device__ __forceinline__ uint64_t bcast2(float v) {
    uint64_t r;
    asm("mov.b64 %0, {%1, %1};" : "=l"(r) : "r"(__float_as_uint(v)));
    return r;
}
__device__ __forceinline__ uint32_t smem_u32(const void* p) {
    uint32_t a;
    asm("{ .reg .u64 t; cvta.to.shared.u64 t, %1; cvt.u32.u64 %0, t; }"
        : "=r"(a) : "l"(p));
    return a;
}
__device__ __forceinline__ void cp_async16(uint32_t dst, const void* src) {
    asm volatile("cp.async.ca.shared.global [%0], [%1], 16;"
                 :: "r"(dst), "l"(src) : "memory");
}
#define CP_COMMIT()  asm volatile("cp.async.commit_group;" ::: "memory")
#define CP_WAIT(n)   asm volatile("cp.async.wait_group %0;" :: "n"(n) : "memory")

// ---------------------------------------------------------------------------
// Kernel 1: zero counts + detect edge_index dtype (JAX may emit int32 even
// though the reference asks for int64).
// ---------------------------------------------------------------------------
__global__ void init_kernel(const void* ei, int E, int N) {
    int i = blockIdx.x * blockDim.x + threadIdx.x;
    if (i <= N) g_cnt[i] = 0;
    if (i == 0) {
        const long long* p64 = (const long long*)ei;
        int ok = 1;
        int cnt = (E < 64) ? E : 64;
        for (int j = 0; j < cnt; j++) {
            long long v = p64[j];
            if (v < 0 || v >= (long long)N) { ok = 0; break; }
        }
        g_is64 = ok;
    }
}

// ---------------------------------------------------------------------------
// Kernel 2: histogram of src + per-edge rank (atomic kept out of permute)
// ---------------------------------------------------------------------------
__global__ __launch_bounds__(256) void count_kernel(const void* __restrict__ ei,
                                                    int E, int N) {
    int e = blockIdx.x * blockDim.x + threadIdx.x;
    if (e >= E) return;
    int src = g_is64 ? (int)__ldg((const long long*)ei + e)
                     : __ldg((const int*)ei + e);
    if ((unsigned)src < (unsigned)N)
        g_rank[e] = atomicAdd(&g_cnt[src], 1);
}

// ---------------------------------------------------------------------------
// Kernel 3: exclusive scan, warp-shuffle two-level (2 barriers total)
// ---------------------------------------------------------------------------
__global__ __launch_bounds__(1024) void scan_kernel(int N) {
    __shared__ int wsum[32];
    int t    = threadIdx.x;
    int lane = t & 31;
    int wrp  = t >> 5;

    int chunk = (N + 1023) / 1024;
    int b0 = t * chunk;
    int b1 = b0 + chunk; if (b1 > N) b1 = N;

    int loc[16];
    int s = 0;
    for (int i = b0; i < b1; i++) { int c = __ldg(&g_cnt[i]); loc[i - b0] = c; s += c; }

    int inc = s;
    #pragma unroll
    for (int d = 1; d < 32; d <<= 1) {
        int v = __shfl_up_sync(0xFFFFFFFFu, inc, d);
        if (lane >= d) inc += v;
    }
    if (lane == 31) wsum[wrp] = inc;
    __syncthreads();

    if (wrp == 0) {
        int v = wsum[lane];
        int wi = v;
        #pragma unroll
        for (int d = 1; d < 32; d <<= 1) {
            int u = __shfl_up_sync(0xFFFFFFFFu, wi, d);
            if (lane >= d) wi += u;
        }
        wsum[lane] = wi - v;
    }
    __syncthreads();

    int run = wsum[wrp] + (inc - s);
    for (int i = b0; i < b1; i++) { g_off[i] = run; run += loc[i - b0]; }
    if (t == 1023) g_off[N] = run;
}

// ---------------------------------------------------------------------------
// Kernel 4: permute edges into src-sorted packed records (atomic-free)
// ---------------------------------------------------------------------------
__global__ __launch_bounds__(256) void permute_kernel(const void* __restrict__ ei,
                                                      const float* __restrict__ X,
                                                      int E, int N) {
    int e = blockIdx.x * blockDim.x + threadIdx.x;
    if (e >= E) return;
    int src, dst;
    if (g_is64) {
        const long long* p = (const long long*)ei;
        src = (int)__ldg(p + e);
        dst = (int)__ldg(p + (size_t)E + e);
    } else {
        const int* p = (const int*)ei;
        src = __ldg(p + e);
        dst = __ldg(p + (size_t)E + e);
    }
    if ((unsigned)src >= (unsigned)N || (unsigned)dst >= (unsigned)N) return;
    float x0 = __ldg(X + (size_t)e * 3 + 0);
    float x1 = __ldg(X + (size_t)e * 3 + 1);
    float x2 = __ldg(X + (size_t)e * 3 + 2);
    int pos = __ldg(&g_off[src]) + __ldg(&g_rank[e]);
    g_packed[pos] = make_float4(x0, x1, x2, __int_as_float(dst));
}

// ---------------------------------------------------------------------------
// Kernel 5: gather-aggregate.  One warp per node; lane owns 4 channels.
// ---------------------------------------------------------------------------
__global__ __launch_bounds__(256) void gather_kernel(
    const float* __restrict__ h, int N) {
    int w    = (blockIdx.x * blockDim.x + threadIdx.x) >> 5;
    int lane = threadIdx.x & 31;
    if (w >= N) return;

    int beg = __ldg(&g_off[w]);
    int end = __ldg(&g_off[w + 1]);

    float4 a0 = make_float4(0.f, 0.f, 0.f, 0.f);
    float4 a1 = a0, a2 = a0;

    int e = beg;
    for (; e + 3 < end; e += 4) {
        float4 p[4];
        #pragma unroll
        for (int j = 0; j < 4; j++) p[j] = __ldg(&g_packed[e + j]);
        float4 hv[4];
        #pragma unroll
        for (int j = 0; j < 4; j++) {
            int d = __float_as_int(p[j].w);
            hv[j] = __ldg(reinterpret_cast<const float4*>(h + (size_t)d * IN_CH) + lane);
        }
        #pragma unroll
        for (int j = 0; j < 4; j++) {
            a0.x += p[j].x*hv[j].x; a0.y += p[j].x*hv[j].y; a0.z += p[j].x*hv[j].z; a0.w += p[j].x*hv[j].w;
            a1.x += p[j].y*hv[j].x; a1.y += p[j].y*hv[j].y; a1.z += p[j].y*hv[j].z; a1.w += p[j].y*hv[j].w;
            a2.x += p[j].z*hv[j].x; a2.y += p[j].z*hv[j].y; a2.z += p[j].z*hv[j].z; a2.w += p[j].z*hv[j].w;
        }
    }
    for (; e < end; e++) {
        float4 p0 = __ldg(&g_packed[e]);
        int d0 = __float_as_int(p0.w);
        float4 h0 = __ldg(reinterpret_cast<const float4*>(h + (size_t)d0 * IN_CH) + lane);
        a0.x += p0.x*h0.x; a0.y += p0.x*h0.y; a0.z += p0.x*h0.z; a0.w += p0.x*h0.w;
        a1.x += p0.y*h0.x; a1.y += p0.y*h0.y; a1.z += p0.y*h0.z; a1.w += p0.y*h0.w;
        a2.x += p0.z*h0.x; a2.y += p0.z*h0.y; a2.z += p0.z*h0.z; a2.w += p0.z*h0.w;
    }

    float4* base = reinterpret_cast<float4*>(g_agg + (size_t)w * (K_HOPS * IN_CH));
    base[lane]      = a0;
    base[32 + lane] = a1;
    base[64 + lane] = a2;
}

// ---------------------------------------------------------------------------
// Kernel 6: GEMM + max + bias.  512 threads (16 warps/SM) for latency hiding.
// f32x2 FMA over node pairs; thread tile 10n x 2o (C[5][2]).
// sA staged async (natural layout, XOR-swizzled segs) + smem->smem transpose;
// sW double-buffered cp.async.  Smem 208 KB, 125 blocks, single wave.
// ---------------------------------------------------------------------------
#define OFF_AT  0                      // [128][TN] transposed, compute operand
#define OFF_NAT (IN_CH * TN)           // [TN][128] natural, swizzled segments
#define OFF_W   (2 * IN_CH * TN)       // two [128][128] buffers
#define GEMM_SMEM_F (2 * IN_CH * TN + 2 * IN_CH * IN_CH)   // 53248 floats

__global__ __launch_bounds__(GTHR, 1) void gemm_max_bias_kernel(
    const float* __restrict__ W,     // [3][128][128]
    const float* __restrict__ bias,  // [128]
    float* __restrict__ out,         // [N][128]
    int N)
{
    extern __shared__ float smem[];
    float* sAT  = smem + OFF_AT;
    float* sAn  = smem + OFF_NAT;
    float* sWb  = smem + OFF_W;

    const int tid = threadIdx.x;
    const int to  = tid & 63;     // o pair group: o = to*2, to*2+1
    const int tw  = tid >> 6;     // node group: nodes tw*10 .. +9
    const int n0  = blockIdx.x * TN;

    const uint32_t aNatBase = smem_u32(sAn);
    const uint32_t wBase    = smem_u32(sWb);

    // cp.async sA hop k into sAn (natural rows, XOR-swizzled 16B segments)
    auto issue_sA = [&](int k) {
        #pragma unroll
        for (int r = 0; r < 5; r++) {
            int idx = tid + r * GTHR;         // 0..2559
            int nn  = idx >> 5;               // row 0..79
            int p   = idx & 31;               // physical seg
            int sl  = p ^ (nn & 7);           // logical seg (swizzle)
            const float* src = g_agg + (size_t)(n0 + nn) * (K_HOPS * IN_CH)
                             + k * IN_CH + sl * 4;
            cp_async16(aNatBase + (uint32_t)idx * 16u, src);
        }
    };
    auto issue_sW = [&](int k, int buf) {
        uint32_t dst = wBase + (uint32_t)buf * IN_CH * IN_CH * 4u;
        const float4* src = reinterpret_cast<const float4*>(
            W + (size_t)k * IN_CH * IN_CH);
        #pragma unroll
        for (int r = 0; r < 8; r++)
            cp_async16(dst + (tid + r * GTHR) * 16, src + tid + r * GTHR);
    };

    // Prologue: G0 = {sA0, W0}; G1 = {W1}
    issue_sA(0); issue_sW(0, 0); CP_COMMIT();
    issue_sW(1, 1); CP_COMMIT();

    float M[10][2];
    #pragma unroll
    for (int j = 0; j < 10; j++) {
        M[j][0] = -3.0e38f;
        M[j][1] = -3.0e38f;
    }

    for (int k = 0; k < K_HOPS; k++) {
        if (k == 0) { CP_WAIT(1); } else { CP_WAIT(0); }
        __syncthreads();              // staged data visible; prev compute done

        // Transpose sAn -> sAT (conflict-free via segment swizzle)
        #pragma unroll
        for (int r = 0; r < 5; r++) {
            int idx = tid + r * GTHR;     // 0..2559
            int nn  = idx % TN;           // lanes span nn
            int sl  = idx / TN;           // logical seg 0..31
            float4 v = *reinterpret_cast<const float4*>(
                sAn + nn * IN_CH + (sl ^ (nn & 7)) * 4);
            sAT[(sl * 4 + 0) * TN + nn] = v.x;
            sAT[(sl * 4 + 1) * TN + nn] = v.y;
            sAT[(sl * 4 + 2) * TN + nn] = v.z;
            sAT[(sl * 4 + 3) * TN + nn] = v.w;
        }
        __syncthreads();              // sAT ready; sAn free for refill

        if (k == 0)      { issue_sA(1); CP_COMMIT(); }
        else if (k == 1) { issue_sA(2); issue_sW(2, 0); CP_COMMIT(); }

        const float* sW = sWb + (size_t)(k & 1) * IN_CH * IN_CH;

        uint64_t C[5][2];
        #pragma unroll
        for (int p = 0; p < 5; p++) { C[p][0] = 0ull; C[p][1] = 0ull; }

        const float* aRow0 = sAT + tw * 10;   // 40B-aligned
        #pragma unroll 8
        for (int i = 0; i < IN_CH; i++) {
            const uint64_t* ap = reinterpret_cast<const uint64_t*>(aRow0 + i * TN);
            uint64_t a0 = ap[0], a1 = ap[1], a2 = ap[2], a3 = ap[3], a4 = ap[4];
            float2 b = *reinterpret_cast<const float2*>(&sW[i * IN_CH + to * 2]);
            uint64_t b0 = bcast2(b.x), b1 = bcast2(b.y);
            ffma2(C[0][0], a0, b0); ffma2(C[0][1], a0, b1);
            ffma2(C[1][0], a1, b0); ffma2(C[1][1], a1, b1);
            ffma2(C[2][0], a2, b0); ffma2(C[2][1], a2, b1);
            ffma2(C[3][0], a3, b0); ffma2(C[3][1], a3, b1);
            ffma2(C[4][0], a4, b0); ffma2(C[4][1], a4, b1);
        }

        // Fold packed pairs into running max (lo half = even node)
        #pragma unroll
        for (int p = 0; p < 5; p++)
            #pragma unroll
            for (int q = 0; q < 2; q++) {
                float lo = __uint_as_float((uint32_t)(C[p][q] & 0xFFFFFFFFull));
                float hi = __uint_as_float((uint32_t)(C[p][q] >> 32));
                M[2 * p][q]     = fmaxf(M[2 * p][q], lo);
                M[2 * p + 1][q] = fmaxf(M[2 * p + 1][q], hi);
            }
    }

    float2 bv = *reinterpret_cast<const float2*>(bias + to * 2);
    #pragma unroll
    for (int j = 0; j < 10; j++) {
        int node = n0 + tw * 10 + j;
        if (node < N) {
            float2 o;
            o.x = M[j][0] + bv.x;
            o.y = M[j][1] + bv.y;
            *reinterpret_cast<float2*>(out + (size_t)node * IN_CH + to * 2) = o;
        }
    }
}

// ---------------------------------------------------------------------------
// Launch.  Inputs (metadata order): h[f32 N*128], X[f32 E*3],
// edge_index[2*E, int32 OR int64], batch_node[f32 N] (unused),
// weight[f32 3*128*128], bias[f32 128].  Output: f32 [N][128].
// ---------------------------------------------------------------------------
extern "C" void kernel_launch(void* const* d_in, const int* in_sizes, int n_in,
                              void* d_out, int out_size) {
    const float* h    = (const float*)d_in[0];
    const float* X    = (const float*)d_in[1];
    const void*  ei   = d_in[2];
    const float* W    = (const float*)d_in[4];
    const float* bias = (const float*)d_in[5];
    float*       out  = (float*)d_out;

    int N = in_sizes[0] / IN_CH;
    int E = in_sizes[1] / K_HOPS;

    const int SMEM_BYTES = GEMM_SMEM_F * (int)sizeof(float);   // 212992
    static int smem_set = 0;
    if (!smem_set) {
        cudaFuncSetAttribute(gemm_max_bias_kernel,
                             cudaFuncAttributeMaxDynamicSharedMemorySize, SMEM_BYTES);
        smem_set = 1;
    }

    init_kernel<<<(N + 1 + 255) / 256, 256>>>(ei, E, N);
    count_kernel<<<(E + 255) / 256, 256>>>(ei, E, N);
    scan_kernel<<<1, 1024>>>(N);
    permute_kernel<<<(E + 255) / 256, 256>>>(ei, X, E, N);
    gather_kernel<<<(N + 7) / 8, 256>>>(h, N);                      // warp per node
    gemm_max_bias_kernel<<<(N + TN - 1) / TN, GTHR, SMEM_BYTES>>>(W, bias, out, N);
}